// round 13
// baseline (speedup 1.0000x reference)
#include <cuda_runtime.h>
#include <math.h>
#include <stdint.h>

#define NEURONS 54
#define NPAD    64
#define NPAD2   56        // glm neuron pad (4*14)
#define QN      14        // neurons per thread (quarter batch)
#define DT      4
#define STEPS   30
#define BATCHES 128
#define KDIM    5625      // 75*75
#define KPAD    5632      // 44*128
#define KC      128       // K chunk for FC
#define NKC     44        // 5632/128
#define GTH     512       // glm threads
#define GW      16        // glm warps

// scratch (zero-initialized device globals)
__device__ float g_pooled[BATCHES * KPAD];          // [b][k]
__device__ float g_fcpart[NKC * BATCHES * NPAD];    // [kc][b][n]
__device__ float g_expxf[BATCHES * NEURONS];        // exp(xf)

// ---------------------------------------------------------------------------
// Kernel 1: pure streaming 8x8 avg-pool. One thread per pooled output,
// 16 independent evict-first LDG.128, no barriers, no smem.
// ---------------------------------------------------------------------------
__global__ void __launch_bounds__(256) pool_kernel(const float* __restrict__ x)
{
    int idx = blockIdx.x * 256 + threadIdx.x;
    if (idx < BATCHES * KDIM) {
        int b  = idx / KDIM;
        int r  = idx - b * KDIM;     // 0..5624
        int rg = r / 75;
        int p  = r - rg * 75;

        const float4* xp = (const float4*)x + ((b * 600 + rg * 8) * 150 + p * 2);
        float s = 0.f;
#pragma unroll
        for (int rr = 0; rr < 8; rr++) {
            float4 a = __ldcs(xp + rr * 150);
            float4 c = __ldcs(xp + rr * 150 + 1);
            s += (a.x + a.y) + (a.z + a.w) + (c.x + c.y) + (c.z + c.w);
        }
        g_pooled[b * KPAD + r] = s * (1.f / 64.f);
    }
    cudaTriggerProgrammaticLaunchCompletion();
}

// ---------------------------------------------------------------------------
// Kernel 2: split-K FC partials. grid = (44, 8 batch-tiles).
// PDL: stage Ws, trigger, then gridDepSync before reading g_pooled.
// ---------------------------------------------------------------------------
__global__ void __launch_bounds__(256) fc_kernel(const float* __restrict__ fc_w)
{
    __shared__ __align__(16) float Ws[NEURONS * KC];

    const int kc  = blockIdx.x;          // 0..43
    const int bt  = blockIdx.y;          // 0..7
    const int tid = threadIdx.x;
    const int k0  = kc * KC;

    for (int i = tid; i < NEURONS * KC; i += 256) {
        int n = i / KC, k = i - n * KC;
        int kg = k0 + k;
        Ws[i] = (kg < KDIM) ? fc_w[n * KDIM + kg] : 0.f;
    }
    cudaTriggerProgrammaticLaunchCompletion();
    __syncthreads();

    cudaGridDependencySynchronize();     // g_pooled ready beyond this point

    const int w = tid >> 5, lane = tid & 31;
    const int b0 = bt * 16 + w * 2;

    float4 p0 = ((const float4*)(g_pooled + (size_t)b0 * KPAD + k0))[lane];
    float4 p1 = ((const float4*)(g_pooled + (size_t)(b0 + 1) * KPAD + k0))[lane];
    const float4* W4 = (const float4*)Ws;

    for (int n = 0; n < NEURONS; n++) {
        float4 wv = W4[n * 32 + lane];
        float a0 = p0.x * wv.x + p0.y * wv.y + p0.z * wv.z + p0.w * wv.w;
        float a1 = p1.x * wv.x + p1.y * wv.y + p1.z * wv.z + p1.w * wv.w;
#pragma unroll
        for (int d = 16; d; d >>= 1) {
            a0 += __shfl_xor_sync(0xffffffffu, a0, d);
            a1 += __shfl_xor_sync(0xffffffffu, a1, d);
        }
        if (lane == 0) {
            g_fcpart[(kc * BATCHES + b0) * NPAD + n]     = a0;
            g_fcpart[(kc * BATCHES + b0 + 1) * NPAD + n] = a1;
        }
    }
}

// ---------------------------------------------------------------------------
// Kernel 3: reduce 44 K-partials, add bias, exponentiate -> g_expxf[b*54+n].
// ---------------------------------------------------------------------------
__global__ void reduce_exp_kernel(const float* __restrict__ fc_b)
{
    cudaTriggerProgrammaticLaunchCompletion();
    cudaGridDependencySynchronize();     // g_fcpart ready

    const int b = blockIdx.x, n = threadIdx.x;
    float a = 0.f;
#pragma unroll 4
    for (int kc = 0; kc < NKC; kc++)
        a += g_fcpart[(kc * BATCHES + b) * NPAD + n];
    if (n < NEURONS)
        g_expxf[b * NEURONS + n] = expf(a + fc_b[n]);
}

// ---------------------------------------------------------------------------
// Kernel 4: 30-step GLM scan in ONE 512-thread CTA (16 warps, 4/SMSP for
// latency hiding; no cross-SM sync).
// Thread t: batch b = t/4, quarter q = t&3 -> neurons q*14..q*14+13 (pad 56).
// Per step: 14x (nib extract + LDS.64 LUT + pe=exf*er, S+=hs, T+=pe) ->
// shfl d={1,2} combines quarters -> eS=__expf(S_b) -> rs=eS*T_b -> butterfly
// d={4,8,16} (even-offset closure over lane>>2: each of the warp's 8 batches
// ONCE) -> lane0 STS wp[par][wid] -> ONE __syncthreads -> 16-way sum ->
// thr = tot/(B*N) -> 14x spike compare (proven pe*eS>thr) + packed updates.
// ---------------------------------------------------------------------------
__global__ void __launch_bounds__(GTH, 1)
glm_kernel(const float* __restrict__ lw, const float* __restrict__ hw,
           float* __restrict__ out)
{
    __shared__ float2 lut[NPAD2 * 17];        // {hs, exp(h-hs)}, pitch 17
    __shared__ __align__(16) float wp[2][GW]; // [parity][warp]

    const int tid = threadIdx.x;
    const int lane = tid & 31, wid = tid >> 5;
    const int b  = tid >> 2;
    const int q  = tid & 3;
    const int n0 = q * QN;

    // ---- independent prologue (overlaps producers via PDL) ----
    for (int e = tid; e < NPAD2 * 16; e += GTH) {
        int n = e >> 4, nib = e & 15;
        float hs = 0.f, hh = 0.f;
        if (n < NEURONS) {
#pragma unroll
            for (int t = 0; t < DT; t++)
                if (nib & (1 << t)) { hs += lw[n * DT + t]; hh += hw[t]; }
        }
        lut[n * 17 + nib] = make_float2(hs, expf(hh - hs));
    }

    cudaGridDependencySynchronize();     // g_expxf ready beyond this point

    float exf[QN];
#pragma unroll
    for (int i = 0; i < QN; i++) {
        const int n = n0 + i;
        exf[i] = (n < NEURONS) ? g_expxf[b * NEURONS + n] : 0.f;
    }

    __syncthreads();                     // LUT visible

    unsigned pack[2] = {0u, 0u};              // 14 x 4-bit histories
    unsigned cntp[3] = {0u, 0u, 0u};          // 14 x 6-bit counters (5/word)
    float pe[QN];

    for (int step = 0; step < STEPS; step++) {
        // compute phase: dual accumulators to break FADD chains
        float sv0 = 0.f, sv1 = 0.f, tv0 = 0.f, tv1 = 0.f;
#pragma unroll
        for (int i = 0; i < QN; i++) {
            unsigned nib = (pack[i >> 3] >> ((i & 7) * 4)) & 15u;
            float2 e = lut[(n0 + i) * 17 + nib];
            pe[i] = exf[i] * e.y;
            if (i & 1) { sv1 += e.x; tv1 += pe[i]; }
            else       { sv0 += e.x; tv0 += pe[i]; }
        }
        float sv = sv0 + sv1, tv = tv0 + tv1;

        // combine the 4 batch quarters (lanes sharing lane>>2)
        sv += __shfl_xor_sync(0xffffffffu, sv, 1);
        tv += __shfl_xor_sync(0xffffffffu, tv, 1);
        sv += __shfl_xor_sync(0xffffffffu, sv, 2);
        tv += __shfl_xor_sync(0xffffffffu, tv, 2);
        const float eS = __expf(sv);
        float rs = eS * tv;              // batch rate-sum (dup across 4 lanes)
        rs += __shfl_xor_sync(0xffffffffu, rs, 4);
        rs += __shfl_xor_sync(0xffffffffu, rs, 8);
        rs += __shfl_xor_sync(0xffffffffu, rs, 16);
        // rs = sum over this warp's 8 distinct batches (each ONCE)

        const int par = step & 1;
        if (lane == 0) wp[par][wid] = rs;
        __syncthreads();

        const float4* wpv = (const float4*)&wp[par][0];
        float4 A = wpv[0], B = wpv[1], C = wpv[2], D = wpv[3];
        const float tot = (((A.x + A.y) + (A.z + A.w)) + ((B.x + B.y) + (B.z + B.w)))
                        + (((C.x + C.y) + (C.z + C.w)) + ((D.x + D.y) + (D.z + D.w)));
        const float thr = tot * (1.0f / (BATCHES * NEURONS));

        // update phase: shift all nibbles, insert spike bits, bump counters
        unsigned np0 = (pack[0] >> 1) & 0x77777777u;
        unsigned np1 = (pack[1] >> 1) & 0x77777777u;
#pragma unroll
        for (int i = 0; i < QN; i++) {
            bool sp = pe[i] * eS > thr;      // proven spike formula
            if (sp) {
                if (i < 8) np0 |= 8u << (i * 4);
                else       np1 |= 8u << ((i - 8) * 4);
                cntp[i / 5] += 1u << (6 * (i % 5));
            }
        }
        pack[0] = np0; pack[1] = np1;
    }

    // softplus(count), stable (count >= 0)
#pragma unroll
    for (int i = 0; i < QN; i++) {
        const int n = n0 + i;
        if (n < NEURONS) {
            float c = (float)((cntp[i / 5] >> (6 * (i % 5))) & 63u);
            out[b * NEURONS + n] = c + log1pf(expf(-c));
        }
    }
}

extern "C" void kernel_launch(void* const* d_in, const int* in_sizes, int n_in,
                              void* d_out, int out_size)
{
    const float* x   = (const float*)d_in[0];  // [128,1,600,600]
    const float* lw  = (const float*)d_in[1];  // [54,4]
    const float* hw  = (const float*)d_in[2];  // [4]
    const float* fcw = (const float*)d_in[3];  // [54,5625]
    const float* fcb = (const float*)d_in[4];  // [54]
    float* out = (float*)d_out;                // [128,54]

    pool_kernel<<<(BATCHES * KDIM + 255) / 256, 256>>>(x);

    cudaLaunchAttribute at[1];
    at[0].id = cudaLaunchAttributeProgrammaticStreamSerialization;
    at[0].val.programmaticStreamSerializationAllowed = 1;

    {   // fc: PDL-dependent on pool
        cudaLaunchConfig_t cfg = {};
        cfg.gridDim  = dim3(NKC, 8, 1);
        cfg.blockDim = dim3(256, 1, 1);
        cfg.attrs = at; cfg.numAttrs = 1; cfg.stream = 0;
        cudaLaunchKernelEx(&cfg, fc_kernel, fcw);
    }
    {   // reduce_exp: PDL-dependent on fc
        cudaLaunchConfig_t cfg = {};
        cfg.gridDim  = dim3(BATCHES, 1, 1);
        cfg.blockDim = dim3(NPAD, 1, 1);
        cfg.attrs = at; cfg.numAttrs = 1; cfg.stream = 0;
        cudaLaunchKernelEx(&cfg, reduce_exp_kernel, fcb);
    }
    {   // glm: PDL-dependent on reduce_exp
        cudaLaunchConfig_t cfg = {};
        cfg.gridDim  = dim3(1, 1, 1);
        cfg.blockDim = dim3(GTH, 1, 1);
        cfg.attrs = at; cfg.numAttrs = 1; cfg.stream = 0;
        cudaLaunchKernelEx(&cfg, glm_kernel, lw, hw, out);
    }
}

// round 14
// speedup vs baseline: 1.1805x; 1.1805x over previous
#include <cuda_runtime.h>
#include <math.h>
#include <stdint.h>

#define NEURONS 54
#define NPAD    64
#define DT      4
#define STEPS   30
#define BATCHES 128
#define KDIM    5625      // 75*75
#define KPAD    5632      // 44*128
#define KC      128       // K chunk for FC
#define NKC     44        // 5632/128
#define CL      8         // cluster size for glm
#define CTHREADS 128
#define WARPS_TOT 32      // CL * 4 warps

// scratch (zero-initialized device globals; pads never written -> stay 0)
__device__ float g_pooled[BATCHES * KPAD];          // [b][k]
__device__ float g_fcpart[NKC * BATCHES * NPAD];    // [kc][b][n]
__device__ float g_expxf[BATCHES * NPAD];           // exp(xf), 0 for pads

__device__ __forceinline__ uint32_t smem_u32(const void* p) {
    uint32_t a;
    asm("{ .reg .u64 t; cvta.to.shared.u64 t, %1; cvt.u32.u64 %0, t; }"
        : "=r"(a) : "l"(p));
    return a;
}

// ---------------------------------------------------------------------------
// Kernel 1: pure streaming 8x8 avg-pool. One thread per pooled output,
// 16 independent evict-first LDG.128, no barriers, no smem.
// PDL trigger at the end: fc launches as the pool drains.
// ---------------------------------------------------------------------------
__global__ void __launch_bounds__(256) pool_kernel(const float* __restrict__ x)
{
    int idx = blockIdx.x * 256 + threadIdx.x;
    if (idx < BATCHES * KDIM) {
        int b  = idx / KDIM;
        int r  = idx - b * KDIM;     // 0..5624
        int rg = r / 75;
        int p  = r - rg * 75;

        const float4* xp = (const float4*)x + ((b * 600 + rg * 8) * 150 + p * 2);
        float s = 0.f;
#pragma unroll
        for (int rr = 0; rr < 8; rr++) {
            float4 a = __ldcs(xp + rr * 150);
            float4 c = __ldcs(xp + rr * 150 + 1);
            s += (a.x + a.y) + (a.z + a.w) + (c.x + c.y) + (c.z + c.w);
        }
        g_pooled[b * KPAD + r] = s * (1.f / 64.f);
    }
    cudaTriggerProgrammaticLaunchCompletion();
}

// ---------------------------------------------------------------------------
// Kernel 2: split-K FC partials. grid = (44, 8 batch-tiles).
// PDL: stage Ws, trigger, then gridDepSync before reading g_pooled.
// ---------------------------------------------------------------------------
__global__ void __launch_bounds__(256) fc_kernel(const float* __restrict__ fc_w)
{
    __shared__ __align__(16) float Ws[NEURONS * KC];

    const int kc  = blockIdx.x;          // 0..43
    const int bt  = blockIdx.y;          // 0..7
    const int tid = threadIdx.x;
    const int k0  = kc * KC;

    for (int i = tid; i < NEURONS * KC; i += 256) {
        int n = i / KC, k = i - n * KC;
        int kg = k0 + k;
        Ws[i] = (kg < KDIM) ? fc_w[n * KDIM + kg] : 0.f;
    }
    cudaTriggerProgrammaticLaunchCompletion();
    __syncthreads();

    cudaGridDependencySynchronize();     // g_pooled ready beyond this point

    const int w = tid >> 5, lane = tid & 31;
    const int b0 = bt * 16 + w * 2;

    float4 p0 = ((const float4*)(g_pooled + (size_t)b0 * KPAD + k0))[lane];
    float4 p1 = ((const float4*)(g_pooled + (size_t)(b0 + 1) * KPAD + k0))[lane];
    const float4* W4 = (const float4*)Ws;

    for (int n = 0; n < NEURONS; n++) {
        float4 wv = W4[n * 32 + lane];
        float a0 = p0.x * wv.x + p0.y * wv.y + p0.z * wv.z + p0.w * wv.w;
        float a1 = p1.x * wv.x + p1.y * wv.y + p1.z * wv.z + p1.w * wv.w;
#pragma unroll
        for (int d = 16; d; d >>= 1) {
            a0 += __shfl_xor_sync(0xffffffffu, a0, d);
            a1 += __shfl_xor_sync(0xffffffffu, a1, d);
        }
        if (lane == 0) {
            g_fcpart[(kc * BATCHES + b0) * NPAD + n]     = a0;
            g_fcpart[(kc * BATCHES + b0 + 1) * NPAD + n] = a1;
        }
    }
}

// ---------------------------------------------------------------------------
// Kernel 3: reduce 44 K-partials + bias + exp, chip-parallel (128 blocks)
// so glm's 8 CTAs don't chew 1.4MB themselves. Writes 0 for pad neurons.
// ---------------------------------------------------------------------------
__global__ void reduce_exp_kernel(const float* __restrict__ fc_b)
{
    cudaTriggerProgrammaticLaunchCompletion();   // let glm launch ASAP
    cudaGridDependencySynchronize();             // g_fcpart ready

    const int b = blockIdx.x, n = threadIdx.x;
    float a = 0.f;
#pragma unroll 4
    for (int kc = 0; kc < NKC; kc++)
        a += g_fcpart[(kc * BATCHES + b) * NPAD + n];
    float v = 0.f;
    if (n < NEURONS) v = expf(a + fc_b[n]);
    g_expxf[b * NPAD + n] = v;
}

// ---------------------------------------------------------------------------
// Kernel 4: 30-step GLM scan over an 8-CTA CLUSTER (R6/R10-proven loop).
// PDL: LUT build + mapa run BEFORE gridDepSync, overlapping fc+reduce.
// Per step: dual 3-level shfl reduce (S_b, T_b) -> eS=__expf(S_b) ->
// rb=eS*T_b -> 2-level shfl (all lanes hold warp total) -> lanes 0..7 each
// store rs to ONE CTA's gat slot (single SIMT instruction, replaces lane0's
// 8 serial stores) -> cluster arrive -> [shadow: prefetch BOTH next LUT
// candidates, premultiplied] -> cluster wait -> local sum of 32 partials.
// ---------------------------------------------------------------------------
__global__ void __launch_bounds__(CTHREADS, 1) __cluster_dims__(CL, 1, 1)
glm_kernel(const float* __restrict__ lw, const float* __restrict__ hw,
           float* __restrict__ out)
{
    __shared__ float2 lut[NPAD * 18];                 // {hs, exp(h-hs)}
    __shared__ __align__(16) float gat[2][WARPS_TOT]; // [parity][global warp]

    const int tid = threadIdx.x;
    const int lane = tid & 31, wid = tid >> 5;
    uint32_t rank;
    asm("mov.u32 %0, %%cluster_ctarank;" : "=r"(rank));
    const int gwid = (int)rank * 4 + wid;

    const int b = (int)rank * 16 + (tid >> 3);
    const int g = tid & 7;

    // ---- independent prologue (overlaps fc/reduce via PDL) ----
    for (int e = tid; e < NPAD * 16; e += CTHREADS) {
        int n = e >> 4, nib = e & 15;
        float hs = 0.f, h = 0.f;
        if (n < NEURONS) {
#pragma unroll
            for (int t = 0; t < DT; t++)
                if (nib & (1 << t)) { hs += lw[n * DT + t]; h += hw[t]; }
        }
        lut[n * 18 + nib] = make_float2(hs, expf(h - hs));
    }

    // my per-lane remote target: CTA (lane&7), slot gwid (buffer 0)
    uint32_t rem_mine;
    {
        uint32_t base = smem_u32(&gat[0][0]) + (uint32_t)gwid * 4u;
        asm("mapa.shared::cluster.u32 %0, %1, %2;"
            : "=r"(rem_mine) : "r"(base), "r"(lane & 7));
    }

    cudaGridDependencySynchronize();     // g_expxf ready beyond this point

    float exf[8];
#pragma unroll
    for (int i = 0; i < 8; i++) exf[i] = g_expxf[b * NPAD + g + 8 * i];

    __syncthreads();
    asm volatile("barrier.cluster.arrive.aligned;" ::: "memory");
    asm volatile("barrier.cluster.wait.aligned;"   ::: "memory");

    // state: pe[i] = exf*er(cur nib), slS = sum hs(cur nib); history all-zero
    unsigned nibs = 0;
    float slS = 0.f;
    float pe[8], cnt[8];
#pragma unroll
    for (int i = 0; i < 8; i++) { pe[i] = exf[i]; cnt[i] = 0.f; }

    for (int step = 0; step < STEPS; step++) {
        float sv = slS, tv = 0.f;
#pragma unroll
        for (int i = 0; i < 8; i++) tv += pe[i];

        // dual per-batch reduce over the 8 g-lanes
#pragma unroll
        for (int d = 1; d <= 4; d <<= 1) {
            sv += __shfl_xor_sync(0xffffffffu, sv, d);
            tv += __shfl_xor_sync(0xffffffffu, tv, d);
        }
        const float eS = __expf(sv);
        float rs = eS * tv;                      // batch rate-sum
        rs += __shfl_xor_sync(0xffffffffu, rs, 8);
        rs += __shfl_xor_sync(0xffffffffu, rs, 16);
        // all 32 lanes now hold this warp's total

        const uint32_t par_off = (step & 1) ? (WARPS_TOT * 4u) : 0u;
        if (lane < CL) {
            asm volatile("st.shared::cluster.f32 [%0], %1;"
                         :: "r"(rem_mine + par_off), "f"(rs) : "memory");
        }
        asm volatile("barrier.cluster.arrive.aligned;" ::: "memory");

        // --- barrier shadow: both next-LUT candidates, premultiplied ---
        float p0[8], p1[8], x0[8], x1[8];
#pragma unroll
        for (int i = 0; i < 8; i++) {
            unsigned nb = ((nibs >> (4 * i)) >> 1) & 7u;
            const float2* basep = &lut[(g + 8 * i) * 18];
            float2 a0 = basep[nb];        // no spike
            float2 a1 = basep[nb | 8u];   // spike
            x0[i] = a0.x; x1[i] = a1.x;
            p0[i] = exf[i] * a0.y; p1[i] = exf[i] * a1.y;
        }

        asm volatile("barrier.cluster.wait.aligned;" ::: "memory");

        // redundant local sum of 32 warp partials
        const float4* gp = (const float4*)&gat[step & 1][0];
        float t0 = 0.f, t1 = 0.f;
#pragma unroll
        for (int q = 0; q < 8; q += 2) {
            float4 v0 = gp[q], v1 = gp[q + 1];
            t0 += (v0.x + v0.y) + (v0.z + v0.w);
            t1 += (v1.x + v1.y) + (v1.z + v1.w);
        }
        const float thr = (t0 + t1) * (1.f / (BATCHES * NEURONS));

        unsigned nn = 0;
        slS = 0.f;
#pragma unroll
        for (int i = 0; i < 8; i++) {
            unsigned nib = (nibs >> (4 * i)) & 15u;
            bool sp = pe[i] * eS > thr;
            cnt[i] += sp ? 1.f : 0.f;
            pe[i]  = sp ? p1[i] : p0[i];
            slS   += sp ? x1[i] : x0[i];
            nn |= (((nib >> 1) | (sp ? 8u : 0u)) & 15u) << (4 * i);
        }
        nibs = nn;
    }

    // softplus(count), stable (count >= 0)
#pragma unroll
    for (int i = 0; i < 8; i++) {
        int n = g + 8 * i;
        if (n < NEURONS) {
            float c = cnt[i];
            out[b * NEURONS + n] = c + log1pf(expf(-c));
        }
    }
}

extern "C" void kernel_launch(void* const* d_in, const int* in_sizes, int n_in,
                              void* d_out, int out_size)
{
    const float* x   = (const float*)d_in[0];  // [128,1,600,600]
    const float* lw  = (const float*)d_in[1];  // [54,4]
    const float* hw  = (const float*)d_in[2];  // [4]
    const float* fcw = (const float*)d_in[3];  // [54,5625]
    const float* fcb = (const float*)d_in[4];  // [54]
    float* out = (float*)d_out;                // [128,54]

    pool_kernel<<<(BATCHES * KDIM + 255) / 256, 256>>>(x);

    cudaLaunchAttribute at[1];
    at[0].id = cudaLaunchAttributeProgrammaticStreamSerialization;
    at[0].val.programmaticStreamSerializationAllowed = 1;

    {   // fc: PDL-dependent on pool
        cudaLaunchConfig_t cfg = {};
        cfg.gridDim  = dim3(NKC, 8, 1);
        cfg.blockDim = dim3(256, 1, 1);
        cfg.attrs = at; cfg.numAttrs = 1; cfg.stream = 0;
        cudaLaunchKernelEx(&cfg, fc_kernel, fcw);
    }
    {   // reduce_exp: PDL-dependent on fc
        cudaLaunchConfig_t cfg = {};
        cfg.gridDim  = dim3(BATCHES, 1, 1);
        cfg.blockDim = dim3(NPAD, 1, 1);
        cfg.attrs = at; cfg.numAttrs = 1; cfg.stream = 0;
        cudaLaunchKernelEx(&cfg, reduce_exp_kernel, fcb);
    }
    {   // glm: PDL-dependent on reduce_exp
        cudaLaunchConfig_t cfg = {};
        cfg.gridDim  = dim3(CL, 1, 1);
        cfg.blockDim = dim3(CTHREADS, 1, 1);
        cfg.attrs = at; cfg.numAttrs = 1; cfg.stream = 0;
        cudaLaunchKernelEx(&cfg, glm_kernel, lw, hw, out);
    }
}